// round 7
// baseline (speedup 1.0000x reference)
#include <cuda_runtime.h>

// LSTM: B x T x I -> last hidden -> FC.  I=4, H=8, O=1, T=512.
// Round-7: 16 lanes per batch (gate-split) -> 131072 threads = 4096 warps
// (6.9/SMSP, 28 warps/SM) to fix the TLP starvation proven across R2-R6.
//   lanes j=0..7  of each 16-lane group: rows i[j], f[j]  ("IF lanes")
//   lanes j=8..15:                       rows g[u], o[u]  ("GO lanes", u=j-8)
// Warp = 2 batch elements. 3 tanh / warp-step (i|g, f|o, c).
// Gate exchange: 1 packed shfl; h rebroadcast: bfly+pack+4 shfl.
// Kept: tanh.approx, folded 0.5 sigmoid scales, k-paired f32x2, 2-step x prefetch.

#define T_SEQ 512
#define IDIM  4
#define HDIM  8

typedef unsigned long long u64;

__device__ __forceinline__ u64 pack2(float a, float b) {
    u64 r; asm("mov.b64 %0,{%1,%2};" : "=l"(r) : "f"(a), "f"(b)); return r;
}
__device__ __forceinline__ float2 unpack2(u64 v) {
    float2 r; asm("mov.b64 {%0,%1},%2;" : "=f"(r.x), "=f"(r.y) : "l"(v)); return r;
}
__device__ __forceinline__ u64 fma2(u64 a, u64 b, u64 c) {
    u64 d; asm("fma.rn.f32x2 %0,%1,%2,%3;" : "=l"(d) : "l"(a), "l"(b), "l"(c)); return d;
}
__device__ __forceinline__ float hadd2(u64 v) {
    float2 t = unpack2(v); return t.x + t.y;
}
__device__ __forceinline__ float tanh_fast(float x) {
    float y; asm("tanh.approx.f32 %0,%1;" : "=f"(y) : "f"(x)); return y;
}

__global__ __launch_bounds__(64, 14)
void lstm_fused_kernel(const float* __restrict__ x,
                       const float* __restrict__ W_ih,
                       const float* __restrict__ W_hh,
                       const float* __restrict__ b_ih,
                       const float* __restrict__ b_hh,
                       const float* __restrict__ W_fc,
                       const float* __restrict__ b_fc,
                       float* __restrict__ out,
                       int B)
{
    const int tid  = threadIdx.x;
    const int lane = tid & 31;
    const int j16  = lane & 15;                     // index within 16-lane group
    const int u    = lane & 7;                      // unit index
    const bool isIF = (j16 < 8);

    int b = blockIdx.x * 4 + (tid >> 4);            // batch element (4 groups/block)
    const bool valid = (b < B);
    if (b >= B) b = B - 1;                          // clamp: keep warp converged

    // ---- this lane's two gate rows ----
    // IF lane: row_a = i-row (j),  row_b = f-row (8+j)   both sigmoid -> scale 0.5
    // GO lane: row_a = g-row (16+u) scale 1.0, row_b = o-row (24+u) scale 0.5
    const int ra = (isIF ? 0 : 16) + u;
    const int rb = ra + 8;
    const float sa = isIF ? 0.5f : 1.0f;
    const float sb = 0.5f;

    u64 wia[2], wib[2];          // input weights, k-paired
    u64 wha[4], whb[4];          // recurrent weights, k-paired
    u64 biasa, biasb;
#pragma unroll
    for (int m = 0; m < 2; ++m) {
        wia[m] = pack2(sa * W_ih[ra * IDIM + 2 * m], sa * W_ih[ra * IDIM + 2 * m + 1]);
        wib[m] = pack2(sb * W_ih[rb * IDIM + 2 * m], sb * W_ih[rb * IDIM + 2 * m + 1]);
    }
#pragma unroll
    for (int m = 0; m < 4; ++m) {
        wha[m] = pack2(sa * W_hh[ra * HDIM + 2 * m], sa * W_hh[ra * HDIM + 2 * m + 1]);
        whb[m] = pack2(sb * W_hh[rb * HDIM + 2 * m], sb * W_hh[rb * HDIM + 2 * m + 1]);
    }
    biasa = pack2(sa * (b_ih[ra] + b_hh[ra]), 0.0f);
    biasb = pack2(sb * (b_ih[rb] + b_hh[rb]), 0.0f);

    // activation constants: IF: i = 0.5*t+0.5 ; GO: g = t (1,0)
    const float ka1 = isIF ? 0.5f : 1.0f;
    const float ka2 = isIF ? 0.5f : 0.0f;

    const float4* __restrict__ xp =
        reinterpret_cast<const float4*>(x) + (size_t)b * T_SEQ;

    float h = 0.0f, c = 0.0f;
    u64 hb0 = 0, hb1 = 0, hb2 = 0, hb3 = 0;          // (h0,h1)..(h6,h7) broadcast pairs

    float4 bufA = xp[0], bufB = xp[1];               // 2-step rolling prefetch

#pragma unroll 1
    for (int t0 = 0; t0 < T_SEQ; t0 += 2) {
        const int tn = (t0 + 2) & (T_SEQ - 1);       // wraps on last iter (harmless)
        const float4 nA = xp[tn + 0];
        const float4 nB = xp[tn + 1];

        const float4 xs[2] = {bufA, bufB};
#pragma unroll
        for (int s = 0; s < 2; ++s) {
            const float4 xc = xs[s];
            const u64 x01 = pack2(xc.x, xc.y);
            const u64 x23 = pack2(xc.z, xc.w);

            // ---- projections for this lane's two rows ----
            u64 aa = fma2(wia[0], x01, biasa);
            u64 ab = fma2(wib[0], x01, biasb);
            aa = fma2(wia[1], x23, aa);
            ab = fma2(wib[1], x23, ab);

            aa = fma2(wha[0], hb0, aa);  ab = fma2(whb[0], hb0, ab);
            aa = fma2(wha[1], hb1, aa);  ab = fma2(whb[1], hb1, ab);
            aa = fma2(wha[2], hb2, aa);  ab = fma2(whb[2], hb2, ab);
            aa = fma2(wha[3], hb3, aa);  ab = fma2(whb[3], hb3, ab);

            const float za = hadd2(aa);              // z_i (IF) or z_g (GO)
            const float zb = hadd2(ab);              // z_f (IF) or z_o (GO)

            // ---- activations: 2 tanh cover all 4 gates across the warp ----
            const float ta = tanh_fast(za);
            const float tb = tanh_fast(zb);
            const float va = fmaf(ka1, ta, ka2);     // i (IF) / g (GO)
            const float vb = fmaf(0.5f, tb, 0.5f);   // f (IF) / o (GO)

            // ---- ship (g,o) from GO lane 8+u to IF lane u ----
            const u64 pv = pack2(va, vb);
            const u64 go = __shfl_sync(0xffffffffu, pv, 8 + u, 16);
            const float2 go2 = unpack2(go);          // (g, o) on IF lanes

            // ---- cell update (valid on IF lanes; GO lanes compute bounded garbage) ----
            c = fmaf(vb, c, va * go2.x);             // f*c + i*g
            const float tc = tanh_fast(c);
            h = go2.y * tc;                          // o * tanh(c)

            // ---- rebroadcast h pairs for next step ----
            const float hn = __shfl_xor_sync(0xffffffffu, h, 1, 16);
            const u64 ph = pack2(h, hn);             // valid on even IF lanes: (h2m, h2m+1)
            hb0 = __shfl_sync(0xffffffffu, ph, 0, 16);
            hb1 = __shfl_sync(0xffffffffu, ph, 2, 16);
            hb2 = __shfl_sync(0xffffffffu, ph, 4, 16);
            hb3 = __shfl_sync(0xffffffffu, ph, 6, 16);
        }

        bufA = nA; bufB = nB;
    }

    // ---- FC head: out[b] = sum_j h_j * W_fc[j] + b_fc (IF lanes hold valid h) ----
    float v = h * __ldg(W_fc + u);
    v += __shfl_xor_sync(0xffffffffu, v, 1, 8);      // reduce within width-8 segment
    v += __shfl_xor_sync(0xffffffffu, v, 2, 8);
    v += __shfl_xor_sync(0xffffffffu, v, 4, 8);

    if (valid && j16 == 0) out[b] = v + __ldg(b_fc);
}

extern "C" void kernel_launch(void* const* d_in, const int* in_sizes, int n_in,
                              void* d_out, int out_size)
{
    const float* x    = (const float*)d_in[0];
    const float* W_ih = (const float*)d_in[1];
    const float* W_hh = (const float*)d_in[2];
    const float* b_ih = (const float*)d_in[3];
    const float* b_hh = (const float*)d_in[4];
    const float* W_fc = (const float*)d_in[5];
    const float* b_fc = (const float*)d_in[6];
    float* out = (float*)d_out;

    const int B = in_sizes[0] / (T_SEQ * IDIM);      // 8192 here
    const int groups_per_block = 4;                  // 64 threads / 16 lanes
    const int grid = (B + groups_per_block - 1) / groups_per_block;

    lstm_fused_kernel<<<grid, 64>>>(x, W_ih, W_hh, b_ih, b_hh, W_fc, b_fc, out, B);
}

// round 8
// speedup vs baseline: 1.2306x; 1.2306x over previous
#include <cuda_runtime.h>

// LSTM: B x T x I -> last hidden -> FC.  I=4, H=8, O=1, T=512.
// Round-8 = Round-4 config (8 lanes/batch, 2048 warps = 3.46/SMSP, best so far)
// with two instruction-count cuts that keep warp count and tanh count fixed:
//   1) k-pair f32x2 packing: x01/x23 and h-pairs are natural register pairs ->
//      zero dup2/pack movs in the recurrence (R4 spent 12/step on them).
//   2) compact h exchange: shfl_xor + pack(even lanes) + 4 pair-broadcasts
//      = 6 ops vs R4's 8 shfl + 8 dup2 = 16.
// Kept: tanh.approx, folded 0.5 sigmoid scales, 4-deep x prefetch.

#define T_SEQ 512
#define IDIM  4
#define HDIM  8

typedef unsigned long long u64;

__device__ __forceinline__ u64 pack2(float a, float b) {
    u64 r; asm("mov.b64 %0,{%1,%2};" : "=l"(r) : "f"(a), "f"(b)); return r;
}
__device__ __forceinline__ float2 unpack2(u64 v) {
    float2 r; asm("mov.b64 {%0,%1},%2;" : "=f"(r.x), "=f"(r.y) : "l"(v)); return r;
}
__device__ __forceinline__ u64 fma2(u64 a, u64 b, u64 c) {
    u64 d; asm("fma.rn.f32x2 %0,%1,%2,%3;" : "=l"(d) : "l"(a), "l"(b), "l"(c)); return d;
}
__device__ __forceinline__ float hadd2(u64 v) {
    float2 t = unpack2(v); return t.x + t.y;
}
__device__ __forceinline__ float tanh_fast(float x) {
    float y; asm("tanh.approx.f32 %0,%1;" : "=f"(y) : "f"(x)); return y;
}

struct LaneW {
    u64 wih[4][2];   // [gate r][k-pair] input weights
    u64 whh[4][4];   // [gate r][k-pair] recurrent weights
    u64 bias[4];     // (bias, 0)
};

// One timestep. h,c updated in place; hp01..hp67 are the packed h pairs.
__device__ __forceinline__ void lstm_step(const LaneW& W, float4 xc, int odd,
                                          float& h, float& c,
                                          u64& hp01, u64& hp23, u64& hp45, u64& hp67)
{
    const u64 x01 = pack2(xc.x, xc.y);
    const u64 x23 = pack2(xc.z, xc.w);

    // input projection + bias (h-independent; overlaps prev chain)
    u64 acc0 = fma2(W.wih[0][0], x01, W.bias[0]);
    u64 acc1 = fma2(W.wih[1][0], x01, W.bias[1]);
    u64 acc2 = fma2(W.wih[2][0], x01, W.bias[2]);
    u64 acc3 = fma2(W.wih[3][0], x01, W.bias[3]);
    acc0 = fma2(W.wih[0][1], x23, acc0);
    acc1 = fma2(W.wih[1][1], x23, acc1);
    acc2 = fma2(W.wih[2][1], x23, acc2);
    acc3 = fma2(W.wih[3][1], x23, acc3);

    // recurrent projection with packed h pairs
    acc0 = fma2(W.whh[0][0], hp01, acc0);
    acc1 = fma2(W.whh[1][0], hp01, acc1);
    acc2 = fma2(W.whh[2][0], hp01, acc2);
    acc3 = fma2(W.whh[3][0], hp01, acc3);
    acc0 = fma2(W.whh[0][1], hp23, acc0);
    acc1 = fma2(W.whh[1][1], hp23, acc1);
    acc2 = fma2(W.whh[2][1], hp23, acc2);
    acc3 = fma2(W.whh[3][1], hp23, acc3);
    acc0 = fma2(W.whh[0][2], hp45, acc0);
    acc1 = fma2(W.whh[1][2], hp45, acc1);
    acc2 = fma2(W.whh[2][2], hp45, acc2);
    acc3 = fma2(W.whh[3][2], hp45, acc3);
    acc0 = fma2(W.whh[0][3], hp67, acc0);
    acc1 = fma2(W.whh[1][3], hp67, acc1);
    acc2 = fma2(W.whh[2][3], hp67, acc2);
    acc3 = fma2(W.whh[3][3], hp67, acc3);

    const float zi = hadd2(acc0);    // pre-scaled by 0.5
    const float zf = hadd2(acc1);
    const float zg = hadd2(acc2);
    const float zo = hadd2(acc3);

    const float ig = fmaf(0.5f, tanh_fast(zi), 0.5f);
    const float fg = fmaf(0.5f, tanh_fast(zf), 0.5f);
    const float gg = tanh_fast(zg);
    const float og = fmaf(0.5f, tanh_fast(zo), 0.5f);
    c = fmaf(fg, c, ig * gg);
    h = og * tanh_fast(c);

    // rebuild packed h pairs: even lane 2m packs (h_2m, h_2m+1); odd lanes'
    // pack is garbage but the broadcasts below only read even lanes.
    const float hx = __shfl_xor_sync(0xffffffffu, h, 1, 8);
    const u64 ph = pack2(h, hx);
    hp01 = __shfl_sync(0xffffffffu, ph, 0, 8);
    hp23 = __shfl_sync(0xffffffffu, ph, 2, 8);
    hp45 = __shfl_sync(0xffffffffu, ph, 4, 8);
    hp67 = __shfl_sync(0xffffffffu, ph, 6, 8);
    (void)odd;
}

__global__ __launch_bounds__(64)
void lstm_fused_kernel(const float* __restrict__ x,
                       const float* __restrict__ W_ih,
                       const float* __restrict__ W_hh,
                       const float* __restrict__ b_ih,
                       const float* __restrict__ b_hh,
                       const float* __restrict__ W_fc,
                       const float* __restrict__ b_fc,
                       float* __restrict__ out,
                       int B)
{
    const int tid = threadIdx.x;
    const int j   = tid & 7;                        // hidden unit owned by this lane
    int b = blockIdx.x * 8 + (tid >> 3);            // batch element
    const bool valid = (b < B);
    if (b >= B) b = B - 1;                          // clamp: keep warp converged

    // ---- per-lane weights, k-paired; sigmoid rows (i,f,o) pre-scaled by 0.5
    // so sigmoid(z) = 0.5*tanh(acc)+0.5. Gate g (tanh) unscaled.
    LaneW W;
    {
        const float sc[4] = {0.5f, 0.5f, 1.0f, 0.5f};
#pragma unroll
        for (int r = 0; r < 4; ++r) {
            const int row = r * HDIM + j;
            const float s = sc[r];
#pragma unroll
            for (int m = 0; m < 2; ++m)
                W.wih[r][m] = pack2(s * W_ih[row * IDIM + 2 * m],
                                    s * W_ih[row * IDIM + 2 * m + 1]);
#pragma unroll
            for (int m = 0; m < 4; ++m)
                W.whh[r][m] = pack2(s * W_hh[row * HDIM + 2 * m],
                                    s * W_hh[row * HDIM + 2 * m + 1]);
            W.bias[r] = pack2(s * (b_ih[row] + b_hh[row]), 0.0f);
        }
    }

    const float4* __restrict__ xp =
        reinterpret_cast<const float4*>(x) + (size_t)b * T_SEQ;

    float h = 0.0f, c = 0.0f;
    u64 hp01 = 0, hp23 = 0, hp45 = 0, hp67 = 0;      // packed h pairs (h=0 init)

    // rolling 4-step prefetch buffer (covers DRAM miss latency, MLP=4)
    float4 buf0 = xp[0], buf1 = xp[1], buf2 = xp[2], buf3 = xp[3];

#pragma unroll 1
    for (int t0 = 0; t0 < T_SEQ; t0 += 4) {
        const int tn = (t0 + 4) & (T_SEQ - 1);      // wraps on last iter (harmless)
        const float4 n0 = xp[tn + 0];
        const float4 n1 = xp[tn + 1];
        const float4 n2 = xp[tn + 2];
        const float4 n3 = xp[tn + 3];

        lstm_step(W, buf0, j & 1, h, c, hp01, hp23, hp45, hp67);
        lstm_step(W, buf1, j & 1, h, c, hp01, hp23, hp45, hp67);
        lstm_step(W, buf2, j & 1, h, c, hp01, hp23, hp45, hp67);
        lstm_step(W, buf3, j & 1, h, c, hp01, hp23, hp45, hp67);

        buf0 = n0; buf1 = n1; buf2 = n2; buf3 = n3;
    }

    // ---- FC head: out[b] = sum_j h_j * W_fc[j] + b_fc ----
    float v = h * __ldg(W_fc + j);
    v += __shfl_xor_sync(0xffffffffu, v, 1, 8);
    v += __shfl_xor_sync(0xffffffffu, v, 2, 8);
    v += __shfl_xor_sync(0xffffffffu, v, 4, 8);

    if (valid && j == 0) out[b] = v + __ldg(b_fc);
}

extern "C" void kernel_launch(void* const* d_in, const int* in_sizes, int n_in,
                              void* d_out, int out_size)
{
    const float* x    = (const float*)d_in[0];
    const float* W_ih = (const float*)d_in[1];
    const float* W_hh = (const float*)d_in[2];
    const float* b_ih = (const float*)d_in[3];
    const float* b_hh = (const float*)d_in[4];
    const float* W_fc = (const float*)d_in[5];
    const float* b_fc = (const float*)d_in[6];
    float* out = (float*)d_out;

    const int B = in_sizes[0] / (T_SEQ * IDIM);     // 8192 here
    const int groups_per_block = 8;                 // 64 threads / 8 lanes
    const int grid = (B + groups_per_block - 1) / groups_per_block;

    lstm_fused_kernel<<<grid, 64>>>(x, W_ih, W_hh, b_ih, b_hh, W_fc, b_fc, out, B);
}

// round 9
// speedup vs baseline: 1.2818x; 1.0417x over previous
#include <cuda_runtime.h>

// LSTM: B x T x I -> last hidden -> FC.  I=4, H=8, O=1, T=512.
// Round-9 = R4 config (8 lanes/batch, 2048 warps) + k-pair f32x2 packing with
// RECEIVER-side pair assembly: 8 parallel scalar shfl broadcasts (1 level, as
// in R4) + 4 pack2 movs on the receiver -> R8's ~48 instr/step at R4's ~106cyc
// chain (R8's sender-side pairing added a serial shfl level and lost).
// Kept: tanh.approx, folded 0.5 sigmoid scales, 4-deep x prefetch.

#define T_SEQ 512
#define IDIM  4
#define HDIM  8

typedef unsigned long long u64;

__device__ __forceinline__ u64 pack2(float a, float b) {
    u64 r; asm("mov.b64 %0,{%1,%2};" : "=l"(r) : "f"(a), "f"(b)); return r;
}
__device__ __forceinline__ float2 unpack2(u64 v) {
    float2 r; asm("mov.b64 {%0,%1},%2;" : "=f"(r.x), "=f"(r.y) : "l"(v)); return r;
}
__device__ __forceinline__ u64 fma2(u64 a, u64 b, u64 c) {
    u64 d; asm("fma.rn.f32x2 %0,%1,%2,%3;" : "=l"(d) : "l"(a), "l"(b), "l"(c)); return d;
}
__device__ __forceinline__ float hadd2(u64 v) {
    float2 t = unpack2(v); return t.x + t.y;
}
__device__ __forceinline__ float tanh_fast(float x) {
    float y; asm("tanh.approx.f32 %0,%1;" : "=f"(y) : "f"(x)); return y;
}

struct LaneW {
    u64 wih[4][2];   // [gate r][k-pair] input weights
    u64 whh[4][4];   // [gate r][k-pair] recurrent weights
    u64 bias[4];     // (bias, 0)
};

// One timestep. h,c updated in place.
__device__ __forceinline__ void lstm_step(const LaneW& W, float4 xc,
                                          float& h, float& c)
{
    // x pairs: free register bitcasts of the float4 quad
    const u64 x01 = pack2(xc.x, xc.y);
    const u64 x23 = pack2(xc.z, xc.w);

    // input projection + bias (h-independent; overlaps prev chain)
    u64 acc0 = fma2(W.wih[0][0], x01, W.bias[0]);
    u64 acc1 = fma2(W.wih[1][0], x01, W.bias[1]);
    u64 acc2 = fma2(W.wih[2][0], x01, W.bias[2]);
    u64 acc3 = fma2(W.wih[3][0], x01, W.bias[3]);
    acc0 = fma2(W.wih[0][1], x23, acc0);
    acc1 = fma2(W.wih[1][1], x23, acc1);
    acc2 = fma2(W.wih[2][1], x23, acc2);
    acc3 = fma2(W.wih[3][1], x23, acc3);

    // 8 parallel scalar broadcasts (1 shfl level), receiver packs pairs
    const float g0 = __shfl_sync(0xffffffffu, h, 0, 8);
    const float g1 = __shfl_sync(0xffffffffu, h, 1, 8);
    const float g2 = __shfl_sync(0xffffffffu, h, 2, 8);
    const float g3 = __shfl_sync(0xffffffffu, h, 3, 8);
    const float g4 = __shfl_sync(0xffffffffu, h, 4, 8);
    const float g5 = __shfl_sync(0xffffffffu, h, 5, 8);
    const float g6 = __shfl_sync(0xffffffffu, h, 6, 8);
    const float g7 = __shfl_sync(0xffffffffu, h, 7, 8);
    const u64 hp01 = pack2(g0, g1);
    const u64 hp23 = pack2(g2, g3);
    const u64 hp45 = pack2(g4, g5);
    const u64 hp67 = pack2(g6, g7);

    // recurrent projection: 16 flat fma2
    acc0 = fma2(W.whh[0][0], hp01, acc0);
    acc1 = fma2(W.whh[1][0], hp01, acc1);
    acc2 = fma2(W.whh[2][0], hp01, acc2);
    acc3 = fma2(W.whh[3][0], hp01, acc3);
    acc0 = fma2(W.whh[0][1], hp23, acc0);
    acc1 = fma2(W.whh[1][1], hp23, acc1);
    acc2 = fma2(W.whh[2][1], hp23, acc2);
    acc3 = fma2(W.whh[3][1], hp23, acc3);
    acc0 = fma2(W.whh[0][2], hp45, acc0);
    acc1 = fma2(W.whh[1][2], hp45, acc1);
    acc2 = fma2(W.whh[2][2], hp45, acc2);
    acc3 = fma2(W.whh[3][2], hp45, acc3);
    acc0 = fma2(W.whh[0][3], hp67, acc0);
    acc1 = fma2(W.whh[1][3], hp67, acc1);
    acc2 = fma2(W.whh[2][3], hp67, acc2);
    acc3 = fma2(W.whh[3][3], hp67, acc3);

    const float zi = hadd2(acc0);    // pre-scaled by 0.5 (sigmoid rows)
    const float zf = hadd2(acc1);
    const float zg = hadd2(acc2);
    const float zo = hadd2(acc3);

    const float ig = fmaf(0.5f, tanh_fast(zi), 0.5f);
    const float fg = fmaf(0.5f, tanh_fast(zf), 0.5f);
    const float gg = tanh_fast(zg);
    const float og = fmaf(0.5f, tanh_fast(zo), 0.5f);
    c = fmaf(fg, c, ig * gg);
    h = og * tanh_fast(c);
}

__global__ __launch_bounds__(64)
void lstm_fused_kernel(const float* __restrict__ x,
                       const float* __restrict__ W_ih,
                       const float* __restrict__ W_hh,
                       const float* __restrict__ b_ih,
                       const float* __restrict__ b_hh,
                       const float* __restrict__ W_fc,
                       const float* __restrict__ b_fc,
                       float* __restrict__ out,
                       int B)
{
    const int tid = threadIdx.x;
    const int j   = tid & 7;                        // hidden unit owned by this lane
    int b = blockIdx.x * 8 + (tid >> 3);            // batch element
    const bool valid = (b < B);
    if (b >= B) b = B - 1;                          // clamp: keep warp converged

    // ---- per-lane weights, k-paired; sigmoid rows (i,f,o) pre-scaled by 0.5
    // so sigmoid(z) = 0.5*tanh(acc)+0.5. Gate g (tanh) unscaled.
    LaneW W;
    {
        const float sc[4] = {0.5f, 0.5f, 1.0f, 0.5f};
#pragma unroll
        for (int r = 0; r < 4; ++r) {
            const int row = r * HDIM + j;
            const float s = sc[r];
#pragma unroll
            for (int m = 0; m < 2; ++m)
                W.wih[r][m] = pack2(s * W_ih[row * IDIM + 2 * m],
                                    s * W_ih[row * IDIM + 2 * m + 1]);
#pragma unroll
            for (int m = 0; m < 4; ++m)
                W.whh[r][m] = pack2(s * W_hh[row * HDIM + 2 * m],
                                    s * W_hh[row * HDIM + 2 * m + 1]);
            W.bias[r] = pack2(s * (b_ih[row] + b_hh[row]), 0.0f);
        }
    }

    const float4* __restrict__ xp =
        reinterpret_cast<const float4*>(x) + (size_t)b * T_SEQ;

    float h = 0.0f, c = 0.0f;

    // rolling 4-step prefetch buffer (covers DRAM miss latency, MLP=4)
    float4 buf0 = xp[0], buf1 = xp[1], buf2 = xp[2], buf3 = xp[3];

#pragma unroll 1
    for (int t0 = 0; t0 < T_SEQ; t0 += 4) {
        const int tn = (t0 + 4) & (T_SEQ - 1);      // wraps on last iter (harmless)
        const float4 n0 = xp[tn + 0];
        const float4 n1 = xp[tn + 1];
        const float4 n2 = xp[tn + 2];
        const float4 n3 = xp[tn + 3];

        lstm_step(W, buf0, h, c);
        lstm_step(W, buf1, h, c);
        lstm_step(W, buf2, h, c);
        lstm_step(W, buf3, h, c);

        buf0 = n0; buf1 = n1; buf2 = n2; buf3 = n3;
    }

    // ---- FC head: out[b] = sum_j h_j * W_fc[j] + b_fc ----
    float v = h * __ldg(W_fc + j);
    v += __shfl_xor_sync(0xffffffffu, v, 1, 8);
    v += __shfl_xor_sync(0xffffffffu, v, 2, 8);
    v += __shfl_xor_sync(0xffffffffu, v, 4, 8);

    if (valid && j == 0) out[b] = v + __ldg(b_fc);
}

extern "C" void kernel_launch(void* const* d_in, const int* in_sizes, int n_in,
                              void* d_out, int out_size)
{
    const float* x    = (const float*)d_in[0];
    const float* W_ih = (const float*)d_in[1];
    const float* W_hh = (const float*)d_in[2];
    const float* b_ih = (const float*)d_in[3];
    const float* b_hh = (const float*)d_in[4];
    const float* W_fc = (const float*)d_in[5];
    const float* b_fc = (const float*)d_in[6];
    float* out = (float*)d_out;

    const int B = in_sizes[0] / (T_SEQ * IDIM);     // 8192 here
    const int groups_per_block = 8;                 // 64 threads / 8 lanes
    const int grid = (B + groups_per_block - 1) / groups_per_block;

    lstm_fused_kernel<<<grid, 64>>>(x, W_ih, W_hh, b_ih, b_hh, W_fc, b_fc, out, B);
}